// round 14
// baseline (speedup 1.0000x reference)
#include <cuda_runtime.h>
#include <cuda_fp16.h>
#include <cstdint>

// Problem constants
#define BB 2
#define LL 2048
#define DD 2048
#define HH 16
#define HD 128
#define TT (BB*LL)            // 4096 tokens
#define QKVN (3*DD)           // 6144
#define OUT_ELEMS ((long)TT*DD)          // 8388608
#define SCORE_ELEMS ((long)BB*HH*LL*LL)  // 134217728

// Scratch (device globals; no allocation allowed)
__device__ __half g_xn[TT*DD];
__device__ __half g_qkv[TT*QKVN];
__device__ __half g_attn[TT*DD];
__device__ float  g_after[TT*DD];          // residual stays fp32
__device__ __half g_yn[TT*DD];
__device__ __half g_hidden[TT*DD];
__device__ __half g_hg[TT*DD];
__device__ __half g_ph[SCORE_ELEMS];       // half copy of softmax P for PV
// fp16 weight copies
__device__ __half g_wqkv_h[(long)QKVN*DD];
__device__ __half g_wout_h[(long)DD*DD];
__device__ __half g_win_h[(long)DD*DD];
__device__ __half g_whid_h[(long)DD*DD];
__device__ __half g_wgate_h[(long)DD*DD];

// ---------------------------------------------------------------------------
// Fused weight pre-conversion: all five fp32 weights -> fp16 in ONE launch.
// ---------------------------------------------------------------------------
__device__ __forceinline__ void cvt4(const float* __restrict__ s,
                                     __half* __restrict__ d, long i) {
    float4 v = ((const float4*)s)[i];
    __half2 h0 = __floats2half2_rn(v.x, v.y);
    __half2 h1 = __floats2half2_rn(v.z, v.w);
    uint2 u;
    u.x = *(uint32_t*)&h0; u.y = *(uint32_t*)&h1;
    ((uint2*)d)[i] = u;
}

#define CVT_N0 ((long)QKVN * DD / 4)       // w_qkv chunks
#define CVT_N1 ((long)DD * DD / 4)         // each square weight
#define CVT_TOTAL (CVT_N0 + 4 * CVT_N1)

__global__ void cvt_all_kernel(const float* __restrict__ s0,
                               const float* __restrict__ s1,
                               const float* __restrict__ s2,
                               const float* __restrict__ s3,
                               const float* __restrict__ s4,
                               __half* __restrict__ d0, __half* __restrict__ d1,
                               __half* __restrict__ d2, __half* __restrict__ d3,
                               __half* __restrict__ d4) {
    long i = (long)blockIdx.x * blockDim.x + threadIdx.x;
    if (i < CVT_N0)                   { cvt4(s0, d0, i); return; }
    i -= CVT_N0;
    if (i < CVT_N1)                   { cvt4(s1, d1, i); return; }
    i -= CVT_N1;
    if (i < CVT_N1)                   { cvt4(s2, d2, i); return; }
    i -= CVT_N1;
    if (i < CVT_N1)                   { cvt4(s3, d3, i); return; }
    i -= CVT_N1;
    if (i < CVT_N1)                   { cvt4(s4, d4, i); }
}

// ---------------------------------------------------------------------------
// Block reductions (256 threads = 8 warps)
// ---------------------------------------------------------------------------
__device__ __forceinline__ float block_reduce_max(float v, float* red) {
    int lane = threadIdx.x & 31, wid = threadIdx.x >> 5;
    #pragma unroll
    for (int o = 16; o; o >>= 1) v = fmaxf(v, __shfl_xor_sync(0xffffffffu, v, o));
    if (lane == 0) red[wid] = v;
    __syncthreads();
    if (wid == 0) {
        float u = (lane < 8) ? red[lane] : -3.4e38f;
        #pragma unroll
        for (int o = 4; o; o >>= 1) u = fmaxf(u, __shfl_xor_sync(0xffffffffu, u, o));
        if (lane == 0) red[0] = u;
    }
    __syncthreads();
    float r = red[0];
    __syncthreads();
    return r;
}

__device__ __forceinline__ float block_reduce_sum(float v, float* red) {
    int lane = threadIdx.x & 31, wid = threadIdx.x >> 5;
    #pragma unroll
    for (int o = 16; o; o >>= 1) v += __shfl_xor_sync(0xffffffffu, v, o);
    if (lane == 0) red[wid] = v;
    __syncthreads();
    if (wid == 0) {
        float u = (lane < 8) ? red[lane] : 0.f;
        #pragma unroll
        for (int o = 4; o; o >>= 1) u += __shfl_xor_sync(0xffffffffu, u, o);
        if (lane == 0) red[0] = u;
    }
    __syncthreads();
    float r = red[0];
    __syncthreads();
    return r;
}

// ---------------------------------------------------------------------------
// RMSNorm: one block per token row of D=2048; half output (GEMM operand)
// ---------------------------------------------------------------------------
__global__ void rmsnorm_kernel(const float* __restrict__ x,
                               const float* __restrict__ g,
                               __half* __restrict__ y) {
    __shared__ float red[32];
    long row = blockIdx.x;
    const float* xr = x + row * DD;
    __half* yr = y + row * DD;
    int tid = threadIdx.x;

    float4 v0 = *(const float4*)&xr[tid * 4];
    float4 v1 = *(const float4*)&xr[1024 + tid * 4];
    float ss = v0.x*v0.x + v0.y*v0.y + v0.z*v0.z + v0.w*v0.w
             + v1.x*v1.x + v1.y*v1.y + v1.z*v1.z + v1.w*v1.w;
    ss = block_reduce_sum(ss, red);
    float norm = rsqrtf(ss * (1.0f / DD) + 1e-6f);

    float4 g0 = *(const float4*)&g[tid * 4];
    float4 g1 = *(const float4*)&g[1024 + tid * 4];
    __half2 h0 = __floats2half2_rn(v0.x * norm * g0.x, v0.y * norm * g0.y);
    __half2 h1 = __floats2half2_rn(v0.z * norm * g0.z, v0.w * norm * g0.w);
    __half2 h2 = __floats2half2_rn(v1.x * norm * g1.x, v1.y * norm * g1.y);
    __half2 h3 = __floats2half2_rn(v1.z * norm * g1.z, v1.w * norm * g1.w);
    uint2 u0, u1;
    u0.x = *(uint32_t*)&h0; u0.y = *(uint32_t*)&h1;
    u1.x = *(uint32_t*)&h2; u1.y = *(uint32_t*)&h3;
    *(uint2*)&yr[tid * 4] = u0;
    *(uint2*)&yr[1024 + tid * 4] = u1;
}

// ---------------------------------------------------------------------------
// Row softmax (L=2048); fp32 output (checked; streamed) + half copy for PV
// ---------------------------------------------------------------------------
__global__ void softmax_kernel(float* __restrict__ S, __half* __restrict__ Ph) {
    __shared__ float red[32];
    long row = blockIdx.x;
    float* p = S + row * (long)LL;
    __half* ph = Ph + row * (long)LL;
    int tid = threadIdx.x;

    float4 v0 = __ldcs((const float4*)&p[tid * 4]);
    float4 v1 = __ldcs((const float4*)&p[1024 + tid * 4]);
    float m = fmaxf(fmaxf(fmaxf(v0.x, v0.y), fmaxf(v0.z, v0.w)),
                    fmaxf(fmaxf(v1.x, v1.y), fmaxf(v1.z, v1.w)));
    m = block_reduce_max(m, red);

    v0.x = __expf(v0.x - m); v0.y = __expf(v0.y - m);
    v0.z = __expf(v0.z - m); v0.w = __expf(v0.w - m);
    v1.x = __expf(v1.x - m); v1.y = __expf(v1.y - m);
    v1.z = __expf(v1.z - m); v1.w = __expf(v1.w - m);

    float s = v0.x + v0.y + v0.z + v0.w + v1.x + v1.y + v1.z + v1.w;
    s = block_reduce_sum(s, red);
    float inv = 1.0f / s;

    v0.x *= inv; v0.y *= inv; v0.z *= inv; v0.w *= inv;
    v1.x *= inv; v1.y *= inv; v1.z *= inv; v1.w *= inv;
    __stcs((float4*)&p[tid * 4], v0);
    __stcs((float4*)&p[1024 + tid * 4], v1);

    __half2 h0 = __floats2half2_rn(v0.x, v0.y);
    __half2 h1 = __floats2half2_rn(v0.z, v0.w);
    __half2 h2 = __floats2half2_rn(v1.x, v1.y);
    __half2 h3 = __floats2half2_rn(v1.z, v1.w);
    uint2 u0, u1;
    u0.x = *(uint32_t*)&h0; u0.y = *(uint32_t*)&h1;
    u1.x = *(uint32_t*)&h2; u1.y = *(uint32_t*)&h3;
    *(uint2*)&ph[tid * 4] = u0;
    *(uint2*)&ph[1024 + tid * 4] = u1;
}

// ---------------------------------------------------------------------------
// Common GEMM building blocks
// ---------------------------------------------------------------------------
__device__ __forceinline__ void cp16(__half* smem_dst, const __half* gmem_src) {
    uint32_t d = (uint32_t)__cvta_generic_to_shared(smem_dst);
    asm volatile("cp.async.cg.shared.global [%0], [%1], 16;\n"
                 :: "r"(d), "l"(gmem_src));
}

__device__ __forceinline__ void ldsm_x4(uint32_t& r0, uint32_t& r1,
                                        uint32_t& r2, uint32_t& r3,
                                        const __half* p) {
    uint32_t a = (uint32_t)__cvta_generic_to_shared(p);
    asm volatile("ldmatrix.sync.aligned.m8n8.x4.shared.b16 {%0,%1,%2,%3}, [%4];"
                 : "=r"(r0), "=r"(r1), "=r"(r2), "=r"(r3) : "r"(a));
}

__device__ __forceinline__ void ldsm_x4t(uint32_t& r0, uint32_t& r1,
                                         uint32_t& r2, uint32_t& r3,
                                         const __half* p) {
    uint32_t a = (uint32_t)__cvta_generic_to_shared(p);
    asm volatile("ldmatrix.sync.aligned.m8n8.x4.trans.shared.b16 {%0,%1,%2,%3}, [%4];"
                 : "=r"(r0), "=r"(r1), "=r"(r2), "=r"(r3) : "r"(a));
}

__device__ __forceinline__ void mma_f16(float* c, uint32_t a0, uint32_t a1,
                                        uint32_t a2, uint32_t a3,
                                        uint32_t b0, uint32_t b1) {
    asm volatile(
        "mma.sync.aligned.m16n8k16.row.col.f32.f16.f16.f32 "
        "{%0,%1,%2,%3}, {%4,%5,%6,%7}, {%8,%9}, {%0,%1,%2,%3};"
        : "+f"(c[0]), "+f"(c[1]), "+f"(c[2]), "+f"(c[3])
        : "r"(a0), "r"(a1), "r"(a2), "r"(a3), "r"(b0), "r"(b1));
}

// ---------------------------------------------------------------------------
// Dense NT GEMM (K=2048 weights): 128 threads, 4 warps (2x2), warp tile 64x64.
// CTA tile 128x128xBK64, double-buffered cp.async, ldmatrix.x4 frags.
// C = epi( A[M,K] * W[N,K]^T ); OUTF fp32 out, STRM .cs stores.
// ---------------------------------------------------------------------------
template<bool OUTF, bool STRM>
__global__ __launch_bounds__(128, 2)
void gemm_w(const __half* __restrict__ A, const __half* __restrict__ Bm,
            void* __restrict__ Cv,
            int K, int lda, int ldb, int ldc,
            float scale,
            const __half* __restrict__ mulp,
            const float* __restrict__ addp,
            int relu) {
    constexpr int BK = 64;
    constexpr int PA = 72;
    constexpr int ASZ = 128 * PA;

    extern __shared__ __half smem[];
    __half* As = smem;
    __half* Bs = smem + 2 * ASZ;

    int tid = threadIdx.x;
    int lane = tid & 31, warp = tid >> 5;
    int wm = warp >> 1;          // 0..1
    int wn = warp & 1;           // 0..1
    int g = lane >> 2, tig = lane & 3;
    int m_base = wm * 64, n_base = wn * 64;
    int row0 = blockIdx.y * 128;
    int col0 = blockIdx.x * 128;

    int a_r = ((lane >> 3) & 1) * 8 + (lane & 7);
    int a_c = ((lane >> 4) & 1) * 8;
    int bnt_r = ((lane >> 4) & 1) * 8 + (lane & 7);
    int bnt_c = ((lane >> 3) & 1) * 8;

    float acc[4][8][4];
    #pragma unroll
    for (int mi = 0; mi < 4; mi++)
        #pragma unroll
        for (int ni = 0; ni < 8; ni++)
            #pragma unroll
            for (int r = 0; r < 4; r++) acc[mi][ni][r] = 0.f;

    auto issue_tile = [&](int k0, int buf) {
        __half* Ab = As + buf * ASZ;
        #pragma unroll
        for (int t = 0; t < 8; t++) {
            int q = tid + t * 128;
            int r = q >> 3;
            int kc = (q & 7) * 8;
            cp16(&Ab[r * PA + kc], &A[(long)(row0 + r) * lda + k0 + kc]);
        }
        __half* Bb = Bs + buf * ASZ;
        #pragma unroll
        for (int t = 0; t < 8; t++) {
            int q = tid + t * 128;
            int r = q >> 3;
            int kc = (q & 7) * 8;
            cp16(&Bb[r * PA + kc], &Bm[(long)(col0 + r) * ldb + k0 + kc]);
        }
        asm volatile("cp.async.commit_group;\n" ::);
    };

    int nk = K / BK;
    issue_tile(0, 0);

    for (int i = 0; i < nk; i++) {
        if (i + 1 < nk) {
            issue_tile((i + 1) * BK, (i + 1) & 1);
            asm volatile("cp.async.wait_group 1;\n" ::);
        } else {
            asm volatile("cp.async.wait_group 0;\n" ::);
        }
        __syncthreads();

        const __half* Ab = As + (i & 1) * ASZ;
        const __half* Bb = Bs + (i & 1) * ASZ;

        #pragma unroll
        for (int kk = 0; kk < BK; kk += 16) {
            uint32_t af[4][4], bf[8][2];
            #pragma unroll
            for (int mi = 0; mi < 4; mi++) {
                const __half* p = Ab + (m_base + mi * 16 + a_r) * PA + kk + a_c;
                ldsm_x4(af[mi][0], af[mi][1], af[mi][2], af[mi][3], p);
            }
            #pragma unroll
            for (int p2 = 0; p2 < 4; p2++) {
                const __half* p = Bb + (n_base + p2 * 16 + bnt_r) * PA + kk + bnt_c;
                ldsm_x4(bf[2 * p2][0], bf[2 * p2][1],
                        bf[2 * p2 + 1][0], bf[2 * p2 + 1][1], p);
            }
            #pragma unroll
            for (int mi = 0; mi < 4; mi++)
                #pragma unroll
                for (int ni = 0; ni < 8; ni++)
                    mma_f16(acc[mi][ni], af[mi][0], af[mi][1], af[mi][2],
                            af[mi][3], bf[ni][0], bf[ni][1]);
        }
        __syncthreads();
    }

    float* Cf = (float*)Cv;
    __half* Ch = (__half*)Cv;
    #pragma unroll
    for (int mi = 0; mi < 4; mi++) {
        #pragma unroll
        for (int half_i = 0; half_i < 2; half_i++) {
            int r = row0 + m_base + mi * 16 + g + half_i * 8;
            #pragma unroll
            for (int ni = 0; ni < 8; ni++) {
                int c = col0 + n_base + ni * 8 + tig * 2;
                long idx = (long)r * ldc + c;
                float2 v;
                v.x = acc[mi][ni][half_i * 2 + 0] * scale;
                v.y = acc[mi][ni][half_i * 2 + 1] * scale;
                if (mulp) {
                    __half2 m2 = *(const __half2*)&mulp[idx];
                    float2 mf = __half22float2(m2);
                    v.x *= mf.x; v.y *= mf.y;
                }
                if (relu) { v.x = fmaxf(v.x, 0.f); v.y = fmaxf(v.y, 0.f); }
                if (addp) {
                    float2 a2 = *(const float2*)&addp[idx];
                    v.x += a2.x; v.y += a2.y;
                }
                if (OUTF) {
                    if (STRM) __stcs((float2*)&Cf[idx], v);
                    else      *(float2*)&Cf[idx] = v;
                } else {
                    *(__half2*)&Ch[idx] = __floats2half2_rn(v.x, v.y);
                }
            }
        }
    }
}

// ---------------------------------------------------------------------------
// FP16 mma.sync GEMM, 8 warps 64x32 (kept for S = QK^T and PV)
// ---------------------------------------------------------------------------
template<bool TB, bool OUTF, bool STRM>
__global__ __launch_bounds__(256, 2)
void gemm_h(const __half* __restrict__ A, const __half* __restrict__ Bm,
            void* __restrict__ Cv,
            int K, int lda, int ldb, int ldc,
            int zH,
            long sAb, long sAh, long sBb, long sBh, long sCb, long sCh,
            float scale,
            const __half* __restrict__ mulp,
            const float* __restrict__ addp,
            int relu) {
    constexpr int BK = 64;
    constexpr int PA = 72;
    constexpr int ASZ = 128 * PA;
    constexpr int PBNN = 136;
    constexpr int BSZ = TB ? 128 * PA : BK * PBNN;

    extern __shared__ __half smem[];
    __half* As = smem;
    __half* Bs = smem + 2 * ASZ;

    int z = blockIdx.z;
    int zb = z / zH, zh = z % zH;
    A  += zb * sAb + zh * sAh;
    Bm += zb * sBb + zh * sBh;
    const __half* mp = mulp ? (mulp + zb * sCb + zh * sCh) : nullptr;
    const float* ap = addp ? (addp + zb * sCb + zh * sCh) : nullptr;
    long cofs = zb * sCb + zh * sCh;

    int tid = threadIdx.x;
    int lane = tid & 31, warp = tid >> 5;
    int wm = warp >> 2;
    int wn = warp & 3;
    int g = lane >> 2, tig = lane & 3;
    int m_base = wm * 64, n_base = wn * 32;
    int row0 = blockIdx.y * 128;
    int col0 = blockIdx.x * 128;

    int a_r = ((lane >> 3) & 1) * 8 + (lane & 7);
    int a_c = ((lane >> 4) & 1) * 8;
    int bnt_r = ((lane >> 4) & 1) * 8 + (lane & 7);
    int bnt_c = ((lane >> 3) & 1) * 8;
    int bnn_r = ((lane >> 3) & 1) * 8 + (lane & 7);
    int bnn_c = ((lane >> 4) & 1) * 8;

    float acc[4][4][4];
    #pragma unroll
    for (int mi = 0; mi < 4; mi++)
        #pragma unroll
        for (int ni = 0; ni < 4; ni++)
            #pragma unroll
            for (int r = 0; r < 4; r++) acc[mi][ni][r] = 0.f;

    auto issue_tile = [&](int k0, int buf) {
        __half* Ab = As + buf * ASZ;
        #pragma unroll
        for (int t = 0; t < 4; t++) {
            int q = tid + t * 256;
            int r = q >> 3;
            int kc = (q & 7) * 8;
            cp16(&Ab[r * PA + kc], &A[(long)(row0 + r) * lda + k0 + kc]);
        }
        __half* Bb = Bs + buf * BSZ;
        if (TB) {
            #pragma unroll
            for (int t = 0; t < 4; t++) {
                int q = tid + t * 256;
                int r = q >> 3;
                int kc = (q & 7) * 8;
                cp16(&Bb[r * PA + kc], &Bm[(long)(col0 + r) * ldb + k0 + kc]);
            }
        } else {
            #pragma unroll
            for (int t = 0; t < 4; t++) {
                int q = tid + t * 256;
                int r = q >> 4;
                int c = (q & 15) * 8;
                cp16(&Bb[r * PBNN + c], &Bm[(long)(k0 + r) * ldb + col0 + c]);
            }
        }
        asm volatile("cp.async.commit_group;\n" ::);
    };

    int nk = K / BK;
    issue_tile(0, 0);

    for (int i = 0; i < nk; i++) {
        if (i + 1 < nk) {
            issue_tile((i + 1) * BK, (i + 1) & 1);
            asm volatile("cp.async.wait_group 1;\n" ::);
        } else {
            asm volatile("cp.async.wait_group 0;\n" ::);
        }
        __syncthreads();

        const __half* Ab = As + (i & 1) * ASZ;
        const __half* Bb = Bs + (i & 1) * BSZ;

        #pragma unroll
        for (int kk = 0; kk < BK; kk += 16) {
            uint32_t af[4][4], bf[4][2];
            #pragma unroll
            for (int mi = 0; mi < 4; mi++) {
                const __half* p = Ab + (m_base + mi * 16 + a_r) * PA + kk + a_c;
                ldsm_x4(af[mi][0], af[mi][1], af[mi][2], af[mi][3], p);
            }
            if (TB) {
                #pragma unroll
                for (int p2 = 0; p2 < 2; p2++) {
                    const __half* p = Bb + (n_base + p2 * 16 + bnt_r) * PA + kk + bnt_c;
                    ldsm_x4(bf[2 * p2][0], bf[2 * p2][1],
                            bf[2 * p2 + 1][0], bf[2 * p2 + 1][1], p);
                }
            } else {
                #pragma unroll
                for (int p2 = 0; p2 < 2; p2++) {
                    const __half* p = Bb + (kk + bnn_r) * PBNN + n_base + p2 * 16 + bnn_c;
                    ldsm_x4t(bf[2 * p2][0], bf[2 * p2][1],
                             bf[2 * p2 + 1][0], bf[2 * p2 + 1][1], p);
                }
            }
            #pragma unroll
            for (int mi = 0; mi < 4; mi++)
                #pragma unroll
                for (int ni = 0; ni < 4; ni++)
                    mma_f16(acc[mi][ni], af[mi][0], af[mi][1], af[mi][2],
                            af[mi][3], bf[ni][0], bf[ni][1]);
        }
        __syncthreads();
    }

    float* Cf = (float*)Cv + cofs;
    __half* Ch = (__half*)Cv + cofs;
    #pragma unroll
    for (int mi = 0; mi < 4; mi++) {
        #pragma unroll
        for (int half_i = 0; half_i < 2; half_i++) {
            int r = row0 + m_base + mi * 16 + g + half_i * 8;
            #pragma unroll
            for (int ni = 0; ni < 4; ni++) {
                int c = col0 + n_base + ni * 8 + tig * 2;
                long idx = (long)r * ldc + c;
                float2 v;
                v.x = acc[mi][ni][half_i * 2 + 0] * scale;
                v.y = acc[mi][ni][half_i * 2 + 1] * scale;
                if (mp) {
                    __half2 m2 = *(const __half2*)&mp[idx];
                    float2 mf = __half22float2(m2);
                    v.x *= mf.x; v.y *= mf.y;
                }
                if (relu) { v.x = fmaxf(v.x, 0.f); v.y = fmaxf(v.y, 0.f); }
                if (ap) {
                    float2 a2 = *(const float2*)&ap[idx];
                    v.x += a2.x; v.y += a2.y;
                }
                if (OUTF) {
                    if (STRM) __stcs((float2*)&Cf[idx], v);
                    else      *(float2*)&Cf[idx] = v;
                } else {
                    *(__half2*)&Ch[idx] = __floats2half2_rn(v.x, v.y);
                }
            }
        }
    }
}

// ---------------------------------------------------------------------------
extern "C" void kernel_launch(void* const* d_in, const int* in_sizes, int n_in,
                              void* d_out, int out_size) {
    (void)in_sizes; (void)n_in; (void)out_size;
    const float* x       = (const float*)d_in[0];
    const float* w_qkv   = (const float*)d_in[1];
    const float* w_out   = (const float*)d_in[2];
    const float* w_in    = (const float*)d_in[3];
    const float* w_hid   = (const float*)d_in[4];
    const float* w_gate  = (const float*)d_in[5];
    const float* g_attng = (const float*)d_in[6];
    const float* g_ffng  = (const float*)d_in[7];
    float* out = (float*)d_out;
    float* scores = out + OUT_ELEMS;

    __half *p_xn, *p_qkv, *p_attn, *p_yn, *p_hidden, *p_hg, *p_ph;
    float *p_after;
    __half *p_wqkv, *p_wout, *p_win, *p_whid, *p_wgate;
    cudaGetSymbolAddress((void**)&p_xn, g_xn);
    cudaGetSymbolAddress((void**)&p_qkv, g_qkv);
    cudaGetSymbolAddress((void**)&p_attn, g_attn);
    cudaGetSymbolAddress((void**)&p_after, g_after);
    cudaGetSymbolAddress((void**)&p_yn, g_yn);
    cudaGetSymbolAddress((void**)&p_hidden, g_hidden);
    cudaGetSymbolAddress((void**)&p_hg, g_hg);
    cudaGetSymbolAddress((void**)&p_ph, g_ph);
    cudaGetSymbolAddress((void**)&p_wqkv, g_wqkv_h);
    cudaGetSymbolAddress((void**)&p_wout, g_wout_h);
    cudaGetSymbolAddress((void**)&p_win, g_win_h);
    cudaGetSymbolAddress((void**)&p_whid, g_whid_h);
    cudaGetSymbolAddress((void**)&p_wgate, g_wgate_h);

    const int SMEM_NT = (2 * 128 * 72 + 2 * 128 * 72) * 2;   // 73728 B
    const int SMEM_NN = (2 * 128 * 72 + 2 * 64 * 136) * 2;   // 71680 B
    cudaFuncSetAttribute(gemm_w<false, false>,
        cudaFuncAttributeMaxDynamicSharedMemorySize, SMEM_NT);
    cudaFuncSetAttribute(gemm_w<true, false>,
        cudaFuncAttributeMaxDynamicSharedMemorySize, SMEM_NT);
    cudaFuncSetAttribute(gemm_w<true, true>,
        cudaFuncAttributeMaxDynamicSharedMemorySize, SMEM_NT);
    cudaFuncSetAttribute(gemm_h<true, true, true>,
        cudaFuncAttributeMaxDynamicSharedMemorySize, SMEM_NT);
    cudaFuncSetAttribute(gemm_h<false, false, false>,
        cudaFuncAttributeMaxDynamicSharedMemorySize, SMEM_NN);

    const long sQb = (long)LL * QKVN;
    const long sSb = (long)HH * LL * LL;
    const long sSh = (long)LL * LL;
    const float iscale = 0.08838834764831845f;  // 1/sqrt(128)

    // 0) fused weight pre-conversion to fp16 (ONE launch)
    cvt_all_kernel<<<(int)((CVT_TOTAL + 255) / 256), 256>>>(
        w_qkv, w_out, w_in, w_hid, w_gate,
        p_wqkv, p_wout, p_win, p_whid, p_wgate);

    // 1) attn-branch RMSNorm (half output)
    rmsnorm_kernel<<<TT, 256>>>(x, g_attng, p_xn);

    // 2) QKV GEMM: [4096,2048] x [6144,2048]^T  (half out; 64x64 warps)
    gemm_w<false, false><<<dim3(QKVN / 128, TT / 128), 128, SMEM_NT>>>(
        p_xn, p_wqkv, p_qkv, DD, DD, DD, QKVN, 1.0f, nullptr, nullptr, 0);

    // 3) S = Q K^T / sqrt(HD), per (b,h): M=N=2048, K=128 (fp32 out, streamed)
    gemm_h<true, true, true><<<dim3(LL / 128, LL / 128, BB * HH), 256, SMEM_NT>>>(
        p_qkv, p_qkv + DD, scores, HD, QKVN, QKVN, LL,
        HH, sQb, HD, sQb, HD, sSb, sSh, iscale, nullptr, nullptr, 0);

    // 4) row softmax (fp32 streamed + half copy for PV)
    softmax_kernel<<<BB * HH * LL, 256>>>(scores, p_ph);

    // 5) attn = P V, per (b,h): M=2048, N=128, K=2048 (NN; half out)
    gemm_h<false, false, false><<<dim3(1, LL / 128, BB * HH), 256, SMEM_NN>>>(
        p_ph, p_qkv + 2 * DD, p_attn, LL, LL, QKVN, DD,
        HH, sSb, sSh, sQb, HD, (long)LL * DD, HD, 1.0f, nullptr, nullptr, 0);

    // 6) after_attn = x + attn * w_out^T  (fp32 out, cached — re-read twice)
    gemm_w<true, false><<<dim3(DD / 128, TT / 128), 128, SMEM_NT>>>(
        p_attn, p_wout, p_after, DD, DD, DD, DD, 1.0f, nullptr, x, 0);

    // 7) FFN-branch RMSNorm (half output)
    rmsnorm_kernel<<<TT, 256>>>(p_after, g_ffng, p_yn);

    // 8) hidden = relu(yn * w_in^T)  (half out)
    gemm_w<false, false><<<dim3(DD / 128, TT / 128), 128, SMEM_NT>>>(
        p_yn, p_win, p_hidden, DD, DD, DD, DD, 1.0f, nullptr, nullptr, 1);

    // 9) hg = hidden * (hidden * w_gate^T)  (half out)
    gemm_w<false, false><<<dim3(DD / 128, TT / 128), 128, SMEM_NT>>>(
        p_hidden, p_wgate, p_hg, DD, DD, DD, DD, 1.0f, p_hidden, nullptr, 0);

    // 10) out = after_attn + hg * w_hidden^T  (fp32 final output, streamed)
    gemm_w<true, true><<<dim3(DD / 128, TT / 128), 128, SMEM_NT>>>(
        p_hg, p_whid, out, DD, DD, DD, DD, 1.0f, nullptr, p_after, 0);
}

// round 15
// speedup vs baseline: 1.0682x; 1.0682x over previous
#include <cuda_runtime.h>
#include <cuda_fp16.h>
#include <cstdint>

// Problem constants
#define BB 2
#define LL 2048
#define DD 2048
#define HH 16
#define HD 128
#define TT (BB*LL)            // 4096 tokens
#define QKVN (3*DD)           // 6144
#define OUT_ELEMS ((long)TT*DD)          // 8388608
#define SCORE_ELEMS ((long)BB*HH*LL*LL)  // 134217728

// Scratch (device globals; no allocation allowed)
__device__ __half g_xn[TT*DD];
__device__ __half g_qkv[TT*QKVN];
__device__ __half g_attn[TT*DD];
__device__ float  g_after[TT*DD];          // residual stays fp32
__device__ __half g_yn[TT*DD];
__device__ __half g_hidden[TT*DD];
__device__ __half g_hg[TT*DD];
__device__ __half g_ph[SCORE_ELEMS];       // half copy of softmax P for PV
// fp16 weight copies
__device__ __half g_wqkv_h[(long)QKVN*DD];
__device__ __half g_wout_h[(long)DD*DD];
__device__ __half g_win_h[(long)DD*DD];
__device__ __half g_whid_h[(long)DD*DD];
__device__ __half g_wgate_h[(long)DD*DD];

// ---------------------------------------------------------------------------
// Fused weight pre-conversion: all five fp32 weights -> fp16 in ONE launch.
// ---------------------------------------------------------------------------
__device__ __forceinline__ void cvt4(const float* __restrict__ s,
                                     __half* __restrict__ d, long i) {
    float4 v = ((const float4*)s)[i];
    __half2 h0 = __floats2half2_rn(v.x, v.y);
    __half2 h1 = __floats2half2_rn(v.z, v.w);
    uint2 u;
    u.x = *(uint32_t*)&h0; u.y = *(uint32_t*)&h1;
    ((uint2*)d)[i] = u;
}

#define CVT_N0 ((long)QKVN * DD / 4)       // w_qkv chunks
#define CVT_N1 ((long)DD * DD / 4)         // each square weight
#define CVT_TOTAL (CVT_N0 + 4 * CVT_N1)

__global__ void cvt_all_kernel(const float* __restrict__ s0,
                               const float* __restrict__ s1,
                               const float* __restrict__ s2,
                               const float* __restrict__ s3,
                               const float* __restrict__ s4,
                               __half* __restrict__ d0, __half* __restrict__ d1,
                               __half* __restrict__ d2, __half* __restrict__ d3,
                               __half* __restrict__ d4) {
    long i = (long)blockIdx.x * blockDim.x + threadIdx.x;
    if (i < CVT_N0)                   { cvt4(s0, d0, i); return; }
    i -= CVT_N0;
    if (i < CVT_N1)                   { cvt4(s1, d1, i); return; }
    i -= CVT_N1;
    if (i < CVT_N1)                   { cvt4(s2, d2, i); return; }
    i -= CVT_N1;
    if (i < CVT_N1)                   { cvt4(s3, d3, i); return; }
    i -= CVT_N1;
    if (i < CVT_N1)                   { cvt4(s4, d4, i); }
}

// ---------------------------------------------------------------------------
// Block reductions (256 threads = 8 warps)
// ---------------------------------------------------------------------------
__device__ __forceinline__ float block_reduce_max(float v, float* red) {
    int lane = threadIdx.x & 31, wid = threadIdx.x >> 5;
    #pragma unroll
    for (int o = 16; o; o >>= 1) v = fmaxf(v, __shfl_xor_sync(0xffffffffu, v, o));
    if (lane == 0) red[wid] = v;
    __syncthreads();
    if (wid == 0) {
        float u = (lane < 8) ? red[lane] : -3.4e38f;
        #pragma unroll
        for (int o = 4; o; o >>= 1) u = fmaxf(u, __shfl_xor_sync(0xffffffffu, u, o));
        if (lane == 0) red[0] = u;
    }
    __syncthreads();
    float r = red[0];
    __syncthreads();
    return r;
}

__device__ __forceinline__ float block_reduce_sum(float v, float* red) {
    int lane = threadIdx.x & 31, wid = threadIdx.x >> 5;
    #pragma unroll
    for (int o = 16; o; o >>= 1) v += __shfl_xor_sync(0xffffffffu, v, o);
    if (lane == 0) red[wid] = v;
    __syncthreads();
    if (wid == 0) {
        float u = (lane < 8) ? red[lane] : 0.f;
        #pragma unroll
        for (int o = 4; o; o >>= 1) u += __shfl_xor_sync(0xffffffffu, u, o);
        if (lane == 0) red[0] = u;
    }
    __syncthreads();
    float r = red[0];
    __syncthreads();
    return r;
}

// ---------------------------------------------------------------------------
// RMSNorm: one block per token row of D=2048; half output (GEMM operand)
// ---------------------------------------------------------------------------
__global__ void rmsnorm_kernel(const float* __restrict__ x,
                               const float* __restrict__ g,
                               __half* __restrict__ y) {
    __shared__ float red[32];
    long row = blockIdx.x;
    const float* xr = x + row * DD;
    __half* yr = y + row * DD;
    int tid = threadIdx.x;

    float4 v0 = *(const float4*)&xr[tid * 4];
    float4 v1 = *(const float4*)&xr[1024 + tid * 4];
    float ss = v0.x*v0.x + v0.y*v0.y + v0.z*v0.z + v0.w*v0.w
             + v1.x*v1.x + v1.y*v1.y + v1.z*v1.z + v1.w*v1.w;
    ss = block_reduce_sum(ss, red);
    float norm = rsqrtf(ss * (1.0f / DD) + 1e-6f);

    float4 g0 = *(const float4*)&g[tid * 4];
    float4 g1 = *(const float4*)&g[1024 + tid * 4];
    __half2 h0 = __floats2half2_rn(v0.x * norm * g0.x, v0.y * norm * g0.y);
    __half2 h1 = __floats2half2_rn(v0.z * norm * g0.z, v0.w * norm * g0.w);
    __half2 h2 = __floats2half2_rn(v1.x * norm * g1.x, v1.y * norm * g1.y);
    __half2 h3 = __floats2half2_rn(v1.z * norm * g1.z, v1.w * norm * g1.w);
    uint2 u0, u1;
    u0.x = *(uint32_t*)&h0; u0.y = *(uint32_t*)&h1;
    u1.x = *(uint32_t*)&h2; u1.y = *(uint32_t*)&h3;
    *(uint2*)&yr[tid * 4] = u0;
    *(uint2*)&yr[1024 + tid * 4] = u1;
}

// ---------------------------------------------------------------------------
// Row softmax (L=2048). Loads DEFAULT (expected L2-resident from the S chunk
// just computed); fp32 stores .cs (checked output, never re-read); Ph default.
// ---------------------------------------------------------------------------
__global__ void softmax_kernel(float* __restrict__ S, __half* __restrict__ Ph) {
    __shared__ float red[32];
    long row = blockIdx.x;
    float* p = S + row * (long)LL;
    __half* ph = Ph + row * (long)LL;
    int tid = threadIdx.x;

    float4 v0 = *(const float4*)&p[tid * 4];
    float4 v1 = *(const float4*)&p[1024 + tid * 4];
    float m = fmaxf(fmaxf(fmaxf(v0.x, v0.y), fmaxf(v0.z, v0.w)),
                    fmaxf(fmaxf(v1.x, v1.y), fmaxf(v1.z, v1.w)));
    m = block_reduce_max(m, red);

    v0.x = __expf(v0.x - m); v0.y = __expf(v0.y - m);
    v0.z = __expf(v0.z - m); v0.w = __expf(v0.w - m);
    v1.x = __expf(v1.x - m); v1.y = __expf(v1.y - m);
    v1.z = __expf(v1.z - m); v1.w = __expf(v1.w - m);

    float s = v0.x + v0.y + v0.z + v0.w + v1.x + v1.y + v1.z + v1.w;
    s = block_reduce_sum(s, red);
    float inv = 1.0f / s;

    v0.x *= inv; v0.y *= inv; v0.z *= inv; v0.w *= inv;
    v1.x *= inv; v1.y *= inv; v1.z *= inv; v1.w *= inv;
    __stcs((float4*)&p[tid * 4], v0);
    __stcs((float4*)&p[1024 + tid * 4], v1);

    __half2 h0 = __floats2half2_rn(v0.x, v0.y);
    __half2 h1 = __floats2half2_rn(v0.z, v0.w);
    __half2 h2 = __floats2half2_rn(v1.x, v1.y);
    __half2 h3 = __floats2half2_rn(v1.z, v1.w);
    uint2 u0, u1;
    u0.x = *(uint32_t*)&h0; u0.y = *(uint32_t*)&h1;
    u1.x = *(uint32_t*)&h2; u1.y = *(uint32_t*)&h3;
    *(uint2*)&ph[tid * 4] = u0;
    *(uint2*)&ph[1024 + tid * 4] = u1;
}

// ---------------------------------------------------------------------------
// FP16 tensor-core GEMM (mma.sync.m16n8k16), fp32 accumulate.
//   TB=true : C = epi( A[M,K] * W[N,K]^T )   (NT, both K-major)
//   TB=false: C = epi( A[M,K] * B[K,N] )     (NN; B frags via ldmatrix.trans)
// CTA tile 128x128xBK64, 256 threads = 8 warps (2x4), warp tile 64x32.
// OUTF: fp32 output; STRM: .cs streaming stores.
// ---------------------------------------------------------------------------
__device__ __forceinline__ void cp16(__half* smem_dst, const __half* gmem_src) {
    uint32_t d = (uint32_t)__cvta_generic_to_shared(smem_dst);
    asm volatile("cp.async.cg.shared.global [%0], [%1], 16;\n"
                 :: "r"(d), "l"(gmem_src));
}

__device__ __forceinline__ void ldsm_x4(uint32_t& r0, uint32_t& r1,
                                        uint32_t& r2, uint32_t& r3,
                                        const __half* p) {
    uint32_t a = (uint32_t)__cvta_generic_to_shared(p);
    asm volatile("ldmatrix.sync.aligned.m8n8.x4.shared.b16 {%0,%1,%2,%3}, [%4];"
                 : "=r"(r0), "=r"(r1), "=r"(r2), "=r"(r3) : "r"(a));
}

__device__ __forceinline__ void ldsm_x4t(uint32_t& r0, uint32_t& r1,
                                         uint32_t& r2, uint32_t& r3,
                                         const __half* p) {
    uint32_t a = (uint32_t)__cvta_generic_to_shared(p);
    asm volatile("ldmatrix.sync.aligned.m8n8.x4.trans.shared.b16 {%0,%1,%2,%3}, [%4];"
                 : "=r"(r0), "=r"(r1), "=r"(r2), "=r"(r3) : "r"(a));
}

__device__ __forceinline__ void mma_f16(float* c, uint32_t a0, uint32_t a1,
                                        uint32_t a2, uint32_t a3,
                                        uint32_t b0, uint32_t b1) {
    asm volatile(
        "mma.sync.aligned.m16n8k16.row.col.f32.f16.f16.f32 "
        "{%0,%1,%2,%3}, {%4,%5,%6,%7}, {%8,%9}, {%0,%1,%2,%3};"
        : "+f"(c[0]), "+f"(c[1]), "+f"(c[2]), "+f"(c[3])
        : "r"(a0), "r"(a1), "r"(a2), "r"(a3), "r"(b0), "r"(b1));
}

template<bool TB, bool OUTF, bool STRM>
__global__ __launch_bounds__(256, 2)
void gemm_h(const __half* __restrict__ A, const __half* __restrict__ Bm,
            void* __restrict__ Cv,
            int K, int lda, int ldb, int ldc,
            int zH,
            long sAb, long sAh, long sBb, long sBh, long sCb, long sCh,
            float scale,
            const __half* __restrict__ mulp,
            const float* __restrict__ addp,
            int relu) {
    constexpr int BK = 64;
    constexpr int PA = 72;
    constexpr int ASZ = 128 * PA;
    constexpr int PBNN = 136;
    constexpr int BSZ = TB ? 128 * PA : BK * PBNN;

    extern __shared__ __half smem[];
    __half* As = smem;
    __half* Bs = smem + 2 * ASZ;

    int z = blockIdx.z;
    int zb = z / zH, zh = z % zH;
    A  += zb * sAb + zh * sAh;
    Bm += zb * sBb + zh * sBh;
    const __half* mp = mulp ? (mulp + zb * sCb + zh * sCh) : nullptr;
    const float* ap = addp ? (addp + zb * sCb + zh * sCh) : nullptr;
    long cofs = zb * sCb + zh * sCh;

    int tid = threadIdx.x;
    int lane = tid & 31, warp = tid >> 5;
    int wm = warp >> 2;
    int wn = warp & 3;
    int g = lane >> 2, tig = lane & 3;
    int m_base = wm * 64, n_base = wn * 32;
    int row0 = blockIdx.y * 128;
    int col0 = blockIdx.x * 128;

    int a_r = ((lane >> 3) & 1) * 8 + (lane & 7);
    int a_c = ((lane >> 4) & 1) * 8;
    int bnt_r = ((lane >> 4) & 1) * 8 + (lane & 7);
    int bnt_c = ((lane >> 3) & 1) * 8;
    int bnn_r = ((lane >> 3) & 1) * 8 + (lane & 7);
    int bnn_c = ((lane >> 4) & 1) * 8;

    float acc[4][4][4];
    #pragma unroll
    for (int mi = 0; mi < 4; mi++)
        #pragma unroll
        for (int ni = 0; ni < 4; ni++)
            #pragma unroll
            for (int r = 0; r < 4; r++) acc[mi][ni][r] = 0.f;

    auto issue_tile = [&](int k0, int buf) {
        __half* Ab = As + buf * ASZ;
        #pragma unroll
        for (int t = 0; t < 4; t++) {
            int q = tid + t * 256;
            int r = q >> 3;
            int kc = (q & 7) * 8;
            cp16(&Ab[r * PA + kc], &A[(long)(row0 + r) * lda + k0 + kc]);
        }
        __half* Bb = Bs + buf * BSZ;
        if (TB) {
            #pragma unroll
            for (int t = 0; t < 4; t++) {
                int q = tid + t * 256;
                int r = q >> 3;
                int kc = (q & 7) * 8;
                cp16(&Bb[r * PA + kc], &Bm[(long)(col0 + r) * ldb + k0 + kc]);
            }
        } else {
            #pragma unroll
            for (int t = 0; t < 4; t++) {
                int q = tid + t * 256;
                int r = q >> 4;
                int c = (q & 15) * 8;
                cp16(&Bb[r * PBNN + c], &Bm[(long)(k0 + r) * ldb + col0 + c]);
            }
        }
        asm volatile("cp.async.commit_group;\n" ::);
    };

    int nk = K / BK;
    issue_tile(0, 0);

    for (int i = 0; i < nk; i++) {
        if (i + 1 < nk) {
            issue_tile((i + 1) * BK, (i + 1) & 1);
            asm volatile("cp.async.wait_group 1;\n" ::);
        } else {
            asm volatile("cp.async.wait_group 0;\n" ::);
        }
        __syncthreads();

        const __half* Ab = As + (i & 1) * ASZ;
        const __half* Bb = Bs + (i & 1) * BSZ;

        #pragma unroll
        for (int kk = 0; kk < BK; kk += 16) {
            uint32_t af[4][4], bf[4][2];
            #pragma unroll
            for (int mi = 0; mi < 4; mi++) {
                const __half* p = Ab + (m_base + mi * 16 + a_r) * PA + kk + a_c;
                ldsm_x4(af[mi][0], af[mi][1], af[mi][2], af[mi][3], p);
            }
            if (TB) {
                #pragma unroll
                for (int p2 = 0; p2 < 2; p2++) {
                    const __half* p = Bb + (n_base + p2 * 16 + bnt_r) * PA + kk + bnt_c;
                    ldsm_x4(bf[2 * p2][0], bf[2 * p2][1],
                            bf[2 * p2 + 1][0], bf[2 * p2 + 1][1], p);
                }
            } else {
                #pragma unroll
                for (int p2 = 0; p2 < 2; p2++) {
                    const __half* p = Bb + (kk + bnn_r) * PBNN + n_base + p2 * 16 + bnn_c;
                    ldsm_x4t(bf[2 * p2][0], bf[2 * p2][1],
                             bf[2 * p2 + 1][0], bf[2 * p2 + 1][1], p);
                }
            }
            #pragma unroll
            for (int mi = 0; mi < 4; mi++)
                #pragma unroll
                for (int ni = 0; ni < 4; ni++)
                    mma_f16(acc[mi][ni], af[mi][0], af[mi][1], af[mi][2],
                            af[mi][3], bf[ni][0], bf[ni][1]);
        }
        __syncthreads();
    }

    float* Cf = (float*)Cv + cofs;
    __half* Ch = (__half*)Cv + cofs;
    #pragma unroll
    for (int mi = 0; mi < 4; mi++) {
        #pragma unroll
        for (int half_i = 0; half_i < 2; half_i++) {
            int r = row0 + m_base + mi * 16 + g + half_i * 8;
            #pragma unroll
            for (int ni = 0; ni < 4; ni++) {
                int c = col0 + n_base + ni * 8 + tig * 2;
                long idx = (long)r * ldc + c;
                float2 v;
                v.x = acc[mi][ni][half_i * 2 + 0] * scale;
                v.y = acc[mi][ni][half_i * 2 + 1] * scale;
                if (mp) {
                    __half2 m2 = *(const __half2*)&mp[idx];
                    float2 mf = __half22float2(m2);
                    v.x *= mf.x; v.y *= mf.y;
                }
                if (relu) { v.x = fmaxf(v.x, 0.f); v.y = fmaxf(v.y, 0.f); }
                if (ap) {
                    float2 a2 = *(const float2*)&ap[idx];
                    v.x += a2.x; v.y += a2.y;
                }
                if (OUTF) {
                    if (STRM) __stcs((float2*)&Cf[idx], v);
                    else      *(float2*)&Cf[idx] = v;
                } else {
                    *(__half2*)&Ch[idx] = __floats2half2_rn(v.x, v.y);
                }
            }
        }
    }
}

// ---------------------------------------------------------------------------
extern "C" void kernel_launch(void* const* d_in, const int* in_sizes, int n_in,
                              void* d_out, int out_size) {
    (void)in_sizes; (void)n_in; (void)out_size;
    const float* x       = (const float*)d_in[0];
    const float* w_qkv   = (const float*)d_in[1];
    const float* w_out   = (const float*)d_in[2];
    const float* w_in    = (const float*)d_in[3];
    const float* w_hid   = (const float*)d_in[4];
    const float* w_gate  = (const float*)d_in[5];
    const float* g_attng = (const float*)d_in[6];
    const float* g_ffng  = (const float*)d_in[7];
    float* out = (float*)d_out;
    float* scores = out + OUT_ELEMS;

    __half *p_xn, *p_qkv, *p_attn, *p_yn, *p_hidden, *p_hg, *p_ph;
    float *p_after;
    __half *p_wqkv, *p_wout, *p_win, *p_whid, *p_wgate;
    cudaGetSymbolAddress((void**)&p_xn, g_xn);
    cudaGetSymbolAddress((void**)&p_qkv, g_qkv);
    cudaGetSymbolAddress((void**)&p_attn, g_attn);
    cudaGetSymbolAddress((void**)&p_after, g_after);
    cudaGetSymbolAddress((void**)&p_yn, g_yn);
    cudaGetSymbolAddress((void**)&p_hidden, g_hidden);
    cudaGetSymbolAddress((void**)&p_hg, g_hg);
    cudaGetSymbolAddress((void**)&p_ph, g_ph);
    cudaGetSymbolAddress((void**)&p_wqkv, g_wqkv_h);
    cudaGetSymbolAddress((void**)&p_wout, g_wout_h);
    cudaGetSymbolAddress((void**)&p_win, g_win_h);
    cudaGetSymbolAddress((void**)&p_whid, g_whid_h);
    cudaGetSymbolAddress((void**)&p_wgate, g_wgate_h);

    const int SMEM_NT = (2 * 128 * 72 + 2 * 128 * 72) * 2;   // 73728 B
    const int SMEM_NN = (2 * 128 * 72 + 2 * 64 * 136) * 2;   // 71680 B
    cudaFuncSetAttribute(gemm_h<true, false, false>,
        cudaFuncAttributeMaxDynamicSharedMemorySize, SMEM_NT);
    cudaFuncSetAttribute(gemm_h<true, true, false>,
        cudaFuncAttributeMaxDynamicSharedMemorySize, SMEM_NT);
    cudaFuncSetAttribute(gemm_h<true, true, true>,
        cudaFuncAttributeMaxDynamicSharedMemorySize, SMEM_NT);
    cudaFuncSetAttribute(gemm_h<false, false, false>,
        cudaFuncAttributeMaxDynamicSharedMemorySize, SMEM_NN);

    const long sQb = (long)LL * QKVN;
    const long sSh = (long)LL * LL;
    const float iscale = 0.08838834764831845f;  // 1/sqrt(128)

    // 0) fused weight pre-conversion to fp16 (ONE launch)
    cvt_all_kernel<<<(int)((CVT_TOTAL + 255) / 256), 256>>>(
        w_qkv, w_out, w_in, w_hid, w_gate,
        p_wqkv, p_wout, p_win, p_whid, p_wgate);

    // 1) attn-branch RMSNorm (half output)
    rmsnorm_kernel<<<TT, 256>>>(x, g_attng, p_xn);

    // 2) QKV GEMM: [4096,2048] x [6144,2048]^T  (half out)
    gemm_h<true, false, false><<<dim3(QKVN / 128, TT / 128, 1), 256, SMEM_NT>>>(
        p_xn, p_wqkv, p_qkv, DD, DD, DD, QKVN,
        1, 0, 0, 0, 0, 0, 0, 1.0f, nullptr, nullptr, 0);

    // 3+4) L2-resident attention chunking: for each (batch, 4-head) slice
    //      (scores slice = 67 MB < L2), compute S then immediately softmax it
    //      so softmax reads hit L2. S stores DEFAULT (retain); softmax fp32
    //      stores .cs (never re-read).
    for (int c = 0; c < 8; c++) {
        int b = c >> 2, h0 = (c & 3) * 4;
        const __half* Qb = p_qkv + (long)b * sQb + h0 * HD;
        const __half* Kb = p_qkv + DD + (long)b * sQb + h0 * HD;
        float* Sb = scores + ((long)b * HH + h0) * sSh;
        __half* Pb = p_ph + ((long)b * HH + h0) * sSh;

        gemm_h<true, true, false><<<dim3(LL / 128, LL / 128, 4), 256, SMEM_NT>>>(
            Qb, Kb, Sb, HD, QKVN, QKVN, LL,
            4, 0, HD, 0, HD, 0, sSh, iscale, nullptr, nullptr, 0);

        softmax_kernel<<<4 * LL, 256>>>(Sb, Pb);
    }

    // 5) attn = P V, per (b,h): M=2048, N=128, K=2048 (NN; half out)
    gemm_h<false, false, false><<<dim3(1, LL / 128, BB * HH), 256, SMEM_NN>>>(
        p_ph, p_qkv + 2 * DD, p_attn, LL, LL, QKVN, DD,
        HH, (long)HH * sSh, sSh, sQb, HD, (long)LL * DD, HD,
        1.0f, nullptr, nullptr, 0);

    // 6) after_attn = x + attn * w_out^T  (fp32 out, cached — re-read twice)
    gemm_h<true, true, false><<<dim3(DD / 128, TT / 128, 1), 256, SMEM_NT>>>(
        p_attn, p_wout, p_after, DD, DD, DD, DD,
        1, 0, 0, 0, 0, 0, 0, 1.0f, nullptr, x, 0);

    // 7) FFN-branch RMSNorm (half output)
    rmsnorm_kernel<<<TT, 256>>>(p_after, g_ffng, p_yn);

    // 8) hidden = relu(yn * w_in^T)  (half out)
    gemm_h<true, false, false><<<dim3(DD / 128, TT / 128, 1), 256, SMEM_NT>>>(
        p_yn, p_win, p_hidden, DD, DD, DD, DD,
        1, 0, 0, 0, 0, 0, 0, 1.0f, nullptr, nullptr, 1);

    // 9) hg = hidden * (hidden * w_gate^T)  (half out)
    gemm_h<true, false, false><<<dim3(DD / 128, TT / 128, 1), 256, SMEM_NT>>>(
        p_hidden, p_wgate, p_hg, DD, DD, DD, DD,
        1, 0, 0, 0, 0, 0, 0, 1.0f, p_hidden, nullptr, 0);

    // 10) out = after_attn + hg * w_hidden^T  (fp32 final output, streamed)
    gemm_h<true, true, true><<<dim3(DD / 128, TT / 128, 1), 256, SMEM_NT>>>(
        p_hg, p_whid, out, DD, DD, DD, DD,
        1, 0, 0, 0, 0, 0, 0, 1.0f, nullptr, p_after, 0);
}

// round 16
// speedup vs baseline: 1.0683x; 1.0001x over previous
#include <cuda_runtime.h>
#include <cuda_fp16.h>
#include <cstdint>

// Problem constants
#define BB 2
#define LL 2048
#define DD 2048
#define HH 16
#define HD 128
#define TT (BB*LL)            // 4096 tokens
#define QKVN (3*DD)           // 6144
#define OUT_ELEMS ((long)TT*DD)          // 8388608
#define SCORE_ELEMS ((long)BB*HH*LL*LL)  // 134217728

// Scratch (device globals; no allocation allowed)
__device__ __half g_xn[TT*DD];
__device__ __half g_qkv[TT*QKVN];
__device__ __half g_attn[TT*DD];
__device__ float  g_after[TT*DD];          // residual stays fp32
__device__ __half g_yn[TT*DD];
__device__ __half g_hidden[TT*DD];
__device__ __half g_hg[TT*DD];
__device__ __half g_ph[SCORE_ELEMS];       // half copy of softmax P for PV
// fp16 weight copies
__device__ __half g_wqkv_h[(long)QKVN*DD];
__device__ __half g_wout_h[(long)DD*DD];
__device__ __half g_win_h[(long)DD*DD];
__device__ __half g_whid_h[(long)DD*DD];
__device__ __half g_wgate_h[(long)DD*DD];

// ---------------------------------------------------------------------------
// Fused weight pre-conversion: all five fp32 weights -> fp16 in ONE launch.
// ---------------------------------------------------------------------------
__device__ __forceinline__ void cvt4(const float* __restrict__ s,
                                     __half* __restrict__ d, long i) {
    float4 v = ((const float4*)s)[i];
    __half2 h0 = __floats2half2_rn(v.x, v.y);
    __half2 h1 = __floats2half2_rn(v.z, v.w);
    uint2 u;
    u.x = *(uint32_t*)&h0; u.y = *(uint32_t*)&h1;
    ((uint2*)d)[i] = u;
}

#define CVT_N0 ((long)QKVN * DD / 4)       // w_qkv chunks
#define CVT_N1 ((long)DD * DD / 4)         // each square weight
#define CVT_TOTAL (CVT_N0 + 4 * CVT_N1)

__global__ void cvt_all_kernel(const float* __restrict__ s0,
                               const float* __restrict__ s1,
                               const float* __restrict__ s2,
                               const float* __restrict__ s3,
                               const float* __restrict__ s4,
                               __half* __restrict__ d0, __half* __restrict__ d1,
                               __half* __restrict__ d2, __half* __restrict__ d3,
                               __half* __restrict__ d4) {
    long i = (long)blockIdx.x * blockDim.x + threadIdx.x;
    if (i < CVT_N0)                   { cvt4(s0, d0, i); return; }
    i -= CVT_N0;
    if (i < CVT_N1)                   { cvt4(s1, d1, i); return; }
    i -= CVT_N1;
    if (i < CVT_N1)                   { cvt4(s2, d2, i); return; }
    i -= CVT_N1;
    if (i < CVT_N1)                   { cvt4(s3, d3, i); return; }
    i -= CVT_N1;
    if (i < CVT_N1)                   { cvt4(s4, d4, i); }
}

// ---------------------------------------------------------------------------
// Block reductions (256 threads = 8 warps)
// ---------------------------------------------------------------------------
__device__ __forceinline__ float block_reduce_max(float v, float* red) {
    int lane = threadIdx.x & 31, wid = threadIdx.x >> 5;
    #pragma unroll
    for (int o = 16; o; o >>= 1) v = fmaxf(v, __shfl_xor_sync(0xffffffffu, v, o));
    if (lane == 0) red[wid] = v;
    __syncthreads();
    if (wid == 0) {
        float u = (lane < 8) ? red[lane] : -3.4e38f;
        #pragma unroll
        for (int o = 4; o; o >>= 1) u = fmaxf(u, __shfl_xor_sync(0xffffffffu, u, o));
        if (lane == 0) red[0] = u;
    }
    __syncthreads();
    float r = red[0];
    __syncthreads();
    return r;
}

__device__ __forceinline__ float block_reduce_sum(float v, float* red) {
    int lane = threadIdx.x & 31, wid = threadIdx.x >> 5;
    #pragma unroll
    for (int o = 16; o; o >>= 1) v += __shfl_xor_sync(0xffffffffu, v, o);
    if (lane == 0) red[wid] = v;
    __syncthreads();
    if (wid == 0) {
        float u = (lane < 8) ? red[lane] : 0.f;
        #pragma unroll
        for (int o = 4; o; o >>= 1) u += __shfl_xor_sync(0xffffffffu, u, o);
        if (lane == 0) red[0] = u;
    }
    __syncthreads();
    float r = red[0];
    __syncthreads();
    return r;
}

// ---------------------------------------------------------------------------
// RMSNorm: one block per token row of D=2048; half output (GEMM operand)
// ---------------------------------------------------------------------------
__global__ void rmsnorm_kernel(const float* __restrict__ x,
                               const float* __restrict__ g,
                               __half* __restrict__ y) {
    __shared__ float red[32];
    long row = blockIdx.x;
    const float* xr = x + row * DD;
    __half* yr = y + row * DD;
    int tid = threadIdx.x;

    float4 v0 = *(const float4*)&xr[tid * 4];
    float4 v1 = *(const float4*)&xr[1024 + tid * 4];
    float ss = v0.x*v0.x + v0.y*v0.y + v0.z*v0.z + v0.w*v0.w
             + v1.x*v1.x + v1.y*v1.y + v1.z*v1.z + v1.w*v1.w;
    ss = block_reduce_sum(ss, red);
    float norm = rsqrtf(ss * (1.0f / DD) + 1e-6f);

    float4 g0 = *(const float4*)&g[tid * 4];
    float4 g1 = *(const float4*)&g[1024 + tid * 4];
    __half2 h0 = __floats2half2_rn(v0.x * norm * g0.x, v0.y * norm * g0.y);
    __half2 h1 = __floats2half2_rn(v0.z * norm * g0.z, v0.w * norm * g0.w);
    __half2 h2 = __floats2half2_rn(v1.x * norm * g1.x, v1.y * norm * g1.y);
    __half2 h3 = __floats2half2_rn(v1.z * norm * g1.z, v1.w * norm * g1.w);
    uint2 u0, u1;
    u0.x = *(uint32_t*)&h0; u0.y = *(uint32_t*)&h1;
    u1.x = *(uint32_t*)&h2; u1.y = *(uint32_t*)&h3;
    *(uint2*)&yr[tid * 4] = u0;
    *(uint2*)&yr[1024 + tid * 4] = u1;
}

// ---------------------------------------------------------------------------
// Row softmax (L=2048). Loads default (L2-resident from S chunk); fp32
// stores .cs (never re-read); Ph default (read soon by PV).
// ---------------------------------------------------------------------------
__global__ void softmax_kernel(float* __restrict__ S, __half* __restrict__ Ph) {
    __shared__ float red[32];
    long row = blockIdx.x;
    float* p = S + row * (long)LL;
    __half* ph = Ph + row * (long)LL;
    int tid = threadIdx.x;

    float4 v0 = *(const float4*)&p[tid * 4];
    float4 v1 = *(const float4*)&p[1024 + tid * 4];
    float m = fmaxf(fmaxf(fmaxf(v0.x, v0.y), fmaxf(v0.z, v0.w)),
                    fmaxf(fmaxf(v1.x, v1.y), fmaxf(v1.z, v1.w)));
    m = block_reduce_max(m, red);

    v0.x = __expf(v0.x - m); v0.y = __expf(v0.y - m);
    v0.z = __expf(v0.z - m); v0.w = __expf(v0.w - m);
    v1.x = __expf(v1.x - m); v1.y = __expf(v1.y - m);
    v1.z = __expf(v1.z - m); v1.w = __expf(v1.w - m);

    float s = v0.x + v0.y + v0.z + v0.w + v1.x + v1.y + v1.z + v1.w;
    s = block_reduce_sum(s, red);
    float inv = 1.0f / s;

    v0.x *= inv; v0.y *= inv; v0.z *= inv; v0.w *= inv;
    v1.x *= inv; v1.y *= inv; v1.z *= inv; v1.w *= inv;
    __stcs((float4*)&p[tid * 4], v0);
    __stcs((float4*)&p[1024 + tid * 4], v1);

    __half2 h0 = __floats2half2_rn(v0.x, v0.y);
    __half2 h1 = __floats2half2_rn(v0.z, v0.w);
    __half2 h2 = __floats2half2_rn(v1.x, v1.y);
    __half2 h3 = __floats2half2_rn(v1.z, v1.w);
    uint2 u0, u1;
    u0.x = *(uint32_t*)&h0; u0.y = *(uint32_t*)&h1;
    u1.x = *(uint32_t*)&h2; u1.y = *(uint32_t*)&h3;
    *(uint2*)&ph[tid * 4] = u0;
    *(uint2*)&ph[1024 + tid * 4] = u1;
}

// ---------------------------------------------------------------------------
// Common GEMM building blocks
// ---------------------------------------------------------------------------
__device__ __forceinline__ void cp16(__half* smem_dst, const __half* gmem_src) {
    uint32_t d = (uint32_t)__cvta_generic_to_shared(smem_dst);
    asm volatile("cp.async.cg.shared.global [%0], [%1], 16;\n"
                 :: "r"(d), "l"(gmem_src));
}

__device__ __forceinline__ void ldsm_x4(uint32_t& r0, uint32_t& r1,
                                        uint32_t& r2, uint32_t& r3,
                                        const __half* p) {
    uint32_t a = (uint32_t)__cvta_generic_to_shared(p);
    asm volatile("ldmatrix.sync.aligned.m8n8.x4.shared.b16 {%0,%1,%2,%3}, [%4];"
                 : "=r"(r0), "=r"(r1), "=r"(r2), "=r"(r3) : "r"(a));
}

__device__ __forceinline__ void ldsm_x4t(uint32_t& r0, uint32_t& r1,
                                         uint32_t& r2, uint32_t& r3,
                                         const __half* p) {
    uint32_t a = (uint32_t)__cvta_generic_to_shared(p);
    asm volatile("ldmatrix.sync.aligned.m8n8.x4.trans.shared.b16 {%0,%1,%2,%3}, [%4];"
                 : "=r"(r0), "=r"(r1), "=r"(r2), "=r"(r3) : "r"(a));
}

__device__ __forceinline__ void mma_f16(float* c, uint32_t a0, uint32_t a1,
                                        uint32_t a2, uint32_t a3,
                                        uint32_t b0, uint32_t b1) {
    asm volatile(
        "mma.sync.aligned.m16n8k16.row.col.f32.f16.f16.f32 "
        "{%0,%1,%2,%3}, {%4,%5,%6,%7}, {%8,%9}, {%0,%1,%2,%3};"
        : "+f"(c[0]), "+f"(c[1]), "+f"(c[2]), "+f"(c[3])
        : "r"(a0), "r"(a1), "r"(a2), "r"(a3), "r"(b0), "r"(b1));
}

// ---------------------------------------------------------------------------
// High-occupancy dense NT GEMM (K=2048): CTA tile 64x128, 8 warps (2x4),
// warp tile 32x32, ~80 regs -> 3 CTAs/SM (24 resident warps).
// C = epi( A[M,K] * W[N,K]^T ); OUTF fp32 out, STRM .cs stores.
// ---------------------------------------------------------------------------
template<bool OUTF, bool STRM>
__global__ __launch_bounds__(256, 3)
void gemm_d(const __half* __restrict__ A, const __half* __restrict__ Bm,
            void* __restrict__ Cv,
            int K, int lda, int ldb, int ldc,
            float scale,
            const __half* __restrict__ mulp,
            const float* __restrict__ addp,
            int relu) {
    constexpr int BK = 64;
    constexpr int PA = 72;
    constexpr int ASZ = 64 * PA;          // A buffer: 64 rows
    constexpr int BSZ = 128 * PA;         // B buffer: 128 rows

    extern __shared__ __half smem[];
    __half* As = smem;                    // 2 buffers
    __half* Bs = smem + 2 * ASZ;          // 2 buffers

    int tid = threadIdx.x;
    int lane = tid & 31, warp = tid >> 5;
    int wm = warp >> 2;          // 0..1 (32 rows each)
    int wn = warp & 3;           // 0..3 (32 cols each)
    int g = lane >> 2, tig = lane & 3;
    int m_base = wm * 32, n_base = wn * 32;
    int row0 = blockIdx.y * 64;
    int col0 = blockIdx.x * 128;

    int a_r = ((lane >> 3) & 1) * 8 + (lane & 7);
    int a_c = ((lane >> 4) & 1) * 8;
    int bnt_r = ((lane >> 4) & 1) * 8 + (lane & 7);
    int bnt_c = ((lane >> 3) & 1) * 8;

    float acc[2][4][4];
    #pragma unroll
    for (int mi = 0; mi < 2; mi++)
        #pragma unroll
        for (int ni = 0; ni < 4; ni++)
            #pragma unroll
            for (int r = 0; r < 4; r++) acc[mi][ni][r] = 0.f;

    auto issue_tile = [&](int k0, int buf) {
        __half* Ab = As + buf * ASZ;
        #pragma unroll
        for (int t = 0; t < 2; t++) {
            int q = tid + t * 256;
            int r = q >> 3;              // 0..63
            int kc = (q & 7) * 8;
            cp16(&Ab[r * PA + kc], &A[(long)(row0 + r) * lda + k0 + kc]);
        }
        __half* Bb = Bs + buf * BSZ;
        #pragma unroll
        for (int t = 0; t < 4; t++) {
            int q = tid + t * 256;
            int r = q >> 3;              // 0..127
            int kc = (q & 7) * 8;
            cp16(&Bb[r * PA + kc], &Bm[(long)(col0 + r) * ldb + k0 + kc]);
        }
        asm volatile("cp.async.commit_group;\n" ::);
    };

    int nk = K / BK;
    issue_tile(0, 0);

    for (int i = 0; i < nk; i++) {
        if (i + 1 < nk) {
            issue_tile((i + 1) * BK, (i + 1) & 1);
            asm volatile("cp.async.wait_group 1;\n" ::);
        } else {
            asm volatile("cp.async.wait_group 0;\n" ::);
        }
        __syncthreads();

        const __half* Ab = As + (i & 1) * ASZ;
        const __half* Bb = Bs + (i & 1) * BSZ;

        #pragma unroll
        for (int kk = 0; kk < BK; kk += 16) {
            uint32_t af[2][4], bf[4][2];
            #pragma unroll
            for (int mi = 0; mi < 2; mi++) {
                const __half* p = Ab + (m_base + mi * 16 + a_r) * PA + kk + a_c;
                ldsm_x4(af[mi][0], af[mi][1], af[mi][2], af[mi][3], p);
            }
            #pragma unroll
            for (int p2 = 0; p2 < 2; p2++) {
                const __half* p = Bb + (n_base + p2 * 16 + bnt_r) * PA + kk + bnt_c;
                ldsm_x4(bf[2 * p2][0], bf[2 * p2][1],
                        bf[2 * p2 + 1][0], bf[2 * p2 + 1][1], p);
            }
            #pragma unroll
            for (int mi = 0; mi < 2; mi++)
                #pragma unroll
                for (int ni = 0; ni < 4; ni++)
                    mma_f16(acc[mi][ni], af[mi][0], af[mi][1], af[mi][2],
                            af[mi][3], bf[ni][0], bf[ni][1]);
        }
        __syncthreads();
    }

    float* Cf = (float*)Cv;
    __half* Ch = (__half*)Cv;
    #pragma unroll
    for (int mi = 0; mi < 2; mi++) {
        #pragma unroll
        for (int half_i = 0; half_i < 2; half_i++) {
            int r = row0 + m_base + mi * 16 + g + half_i * 8;
            #pragma unroll
            for (int ni = 0; ni < 4; ni++) {
                int c = col0 + n_base + ni * 8 + tig * 2;
                long idx = (long)r * ldc + c;
                float2 v;
                v.x = acc[mi][ni][half_i * 2 + 0] * scale;
                v.y = acc[mi][ni][half_i * 2 + 1] * scale;
                if (mulp) {
                    __half2 m2 = *(const __half2*)&mulp[idx];
                    float2 mf = __half22float2(m2);
                    v.x *= mf.x; v.y *= mf.y;
                }
                if (relu) { v.x = fmaxf(v.x, 0.f); v.y = fmaxf(v.y, 0.f); }
                if (addp) {
                    float2 a2 = *(const float2*)&addp[idx];
                    v.x += a2.x; v.y += a2.y;
                }
                if (OUTF) {
                    if (STRM) __stcs((float2*)&Cf[idx], v);
                    else      *(float2*)&Cf[idx] = v;
                } else {
                    *(__half2*)&Ch[idx] = __floats2half2_rn(v.x, v.y);
                }
            }
        }
    }
}

// ---------------------------------------------------------------------------
// FP16 mma.sync GEMM, 8 warps 64x32 (kept for S = QK^T and PV)
// ---------------------------------------------------------------------------
template<bool TB, bool OUTF, bool STRM>
__global__ __launch_bounds__(256, 2)
void gemm_h(const __half* __restrict__ A, const __half* __restrict__ Bm,
            void* __restrict__ Cv,
            int K, int lda, int ldb, int ldc,
            int zH,
            long sAb, long sAh, long sBb, long sBh, long sCb, long sCh,
            float scale,
            const __half* __restrict__ mulp,
            const float* __restrict__ addp,
            int relu) {
    constexpr int BK = 64;
    constexpr int PA = 72;
    constexpr int ASZ = 128 * PA;
    constexpr int PBNN = 136;
    constexpr int BSZ = TB ? 128 * PA : BK * PBNN;

    extern __shared__ __half smem[];
    __half* As = smem;
    __half* Bs = smem + 2 * ASZ;

    int z = blockIdx.z;
    int zb = z / zH, zh = z % zH;
    A  += zb * sAb + zh * sAh;
    Bm += zb * sBb + zh * sBh;
    const __half* mp = mulp ? (mulp + zb * sCb + zh * sCh) : nullptr;
    const float* ap = addp ? (addp + zb * sCb + zh * sCh) : nullptr;
    long cofs = zb * sCb + zh * sCh;

    int tid = threadIdx.x;
    int lane = tid & 31, warp = tid >> 5;
    int wm = warp >> 2;
    int wn = warp & 3;
    int g = lane >> 2, tig = lane & 3;
    int m_base = wm * 64, n_base = wn * 32;
    int row0 = blockIdx.y * 128;
    int col0 = blockIdx.x * 128;

    int a_r = ((lane >> 3) & 1) * 8 + (lane & 7);
    int a_c = ((lane >> 4) & 1) * 8;
    int bnt_r = ((lane >> 4) & 1) * 8 + (lane & 7);
    int bnt_c = ((lane >> 3) & 1) * 8;
    int bnn_r = ((lane >> 3) & 1) * 8 + (lane & 7);
    int bnn_c = ((lane >> 4) & 1) * 8;

    float acc[4][4][4];
    #pragma unroll
    for (int mi = 0; mi < 4; mi++)
        #pragma unroll
        for (int ni = 0; ni < 4; ni++)
            #pragma unroll
            for (int r = 0; r < 4; r++) acc[mi][ni][r] = 0.f;

    auto issue_tile = [&](int k0, int buf) {
        __half* Ab = As + buf * ASZ;
        #pragma unroll
        for (int t = 0; t < 4; t++) {
            int q = tid + t * 256;
            int r = q >> 3;
            int kc = (q & 7) * 8;
            cp16(&Ab[r * PA + kc], &A[(long)(row0 + r) * lda + k0 + kc]);
        }
        __half* Bb = Bs + buf * BSZ;
        if (TB) {
            #pragma unroll
            for (int t = 0; t < 4; t++) {
                int q = tid + t * 256;
                int r = q >> 3;
                int kc = (q & 7) * 8;
                cp16(&Bb[r * PA + kc], &Bm[(long)(col0 + r) * ldb + k0 + kc]);
            }
        } else {
            #pragma unroll
            for (int t = 0; t < 4; t++) {
                int q = tid + t * 256;
                int r = q >> 4;
                int c = (q & 15) * 8;
                cp16(&Bb[r * PBNN + c], &Bm[(long)(k0 + r) * ldb + col0 + c]);
            }
        }
        asm volatile("cp.async.commit_group;\n" ::);
    };

    int nk = K / BK;
    issue_tile(0, 0);

    for (int i = 0; i < nk; i++) {
        if (i + 1 < nk) {
            issue_tile((i + 1) * BK, (i + 1) & 1);
            asm volatile("cp.async.wait_group 1;\n" ::);
        } else {
            asm volatile("cp.async.wait_group 0;\n" ::);
        }
        __syncthreads();

        const __half* Ab = As + (i & 1) * ASZ;
        const __half* Bb = Bs + (i & 1) * BSZ;

        #pragma unroll
        for (int kk = 0; kk < BK; kk += 16) {
            uint32_t af[4][4], bf[4][2];
            #pragma unroll
            for (int mi = 0; mi < 4; mi++) {
                const __half* p = Ab + (m_base + mi * 16 + a_r) * PA + kk + a_c;
                ldsm_x4(af[mi][0], af[mi][1], af[mi][2], af[mi][3], p);
            }
            if (TB) {
                #pragma unroll
                for (int p2 = 0; p2 < 2; p2++) {
                    const __half* p = Bb + (n_base + p2 * 16 + bnt_r) * PA + kk + bnt_c;
                    ldsm_x4(bf[2 * p2][0], bf[2 * p2][1],
                            bf[2 * p2 + 1][0], bf[2 * p2 + 1][1], p);
                }
            } else {
                #pragma unroll
                for (int p2 = 0; p2 < 2; p2++) {
                    const __half* p = Bb + (kk + bnn_r) * PBNN + n_base + p2 * 16 + bnn_c;
                    ldsm_x4t(bf[2 * p2][0], bf[2 * p2][1],
                             bf[2 * p2 + 1][0], bf[2 * p2 + 1][1], p);
                }
            }
            #pragma unroll
            for (int mi = 0; mi < 4; mi++)
                #pragma unroll
                for (int ni = 0; ni < 4; ni++)
                    mma_f16(acc[mi][ni], af[mi][0], af[mi][1], af[mi][2],
                            af[mi][3], bf[ni][0], bf[ni][1]);
        }
        __syncthreads();
    }

    float* Cf = (float*)Cv + cofs;
    __half* Ch = (__half*)Cv + cofs;
    #pragma unroll
    for (int mi = 0; mi < 4; mi++) {
        #pragma unroll
        for (int half_i = 0; half_i < 2; half_i++) {
            int r = row0 + m_base + mi * 16 + g + half_i * 8;
            #pragma unroll
            for (int ni = 0; ni < 4; ni++) {
                int c = col0 + n_base + ni * 8 + tig * 2;
                long idx = (long)r * ldc + c;
                float2 v;
                v.x = acc[mi][ni][half_i * 2 + 0] * scale;
                v.y = acc[mi][ni][half_i * 2 + 1] * scale;
                if (mp) {
                    __half2 m2 = *(const __half2*)&mp[idx];
                    float2 mf = __half22float2(m2);
                    v.x *= mf.x; v.y *= mf.y;
                }
                if (relu) { v.x = fmaxf(v.x, 0.f); v.y = fmaxf(v.y, 0.f); }
                if (ap) {
                    float2 a2 = *(const float2*)&ap[idx];
                    v.x += a2.x; v.y += a2.y;
                }
                if (OUTF) {
                    if (STRM) __stcs((float2*)&Cf[idx], v);
                    else      *(float2*)&Cf[idx] = v;
                } else {
                    *(__half2*)&Ch[idx] = __floats2half2_rn(v.x, v.y);
                }
            }
        }
    }
}

// ---------------------------------------------------------------------------
extern "C" void kernel_launch(void* const* d_in, const int* in_sizes, int n_in,
                              void* d_out, int out_size) {
    (void)in_sizes; (void)n_in; (void)out_size;
    const float* x       = (const float*)d_in[0];
    const float* w_qkv   = (const float*)d_in[1];
    const float* w_out   = (const float*)d_in[2];
    const float* w_in    = (const float*)d_in[3];
    const float* w_hid   = (const float*)d_in[4];
    const float* w_gate  = (const float*)d_in[5];
    const float* g_attng = (const float*)d_in[6];
    const float* g_ffng  = (const float*)d_in[7];
    float* out = (float*)d_out;
    float* scores = out + OUT_ELEMS;

    __half *p_xn, *p_qkv, *p_attn, *p_yn, *p_hidden, *p_hg, *p_ph;
    float *p_after;
    __half *p_wqkv, *p_wout, *p_win, *p_whid, *p_wgate;
    cudaGetSymbolAddress((void**)&p_xn, g_xn);
    cudaGetSymbolAddress((void**)&p_qkv, g_qkv);
    cudaGetSymbolAddress((void**)&p_attn, g_attn);
    cudaGetSymbolAddress((void**)&p_after, g_after);
    cudaGetSymbolAddress((void**)&p_yn, g_yn);
    cudaGetSymbolAddress((void**)&p_hidden, g_hidden);
    cudaGetSymbolAddress((void**)&p_hg, g_hg);
    cudaGetSymbolAddress((void**)&p_ph, g_ph);
    cudaGetSymbolAddress((void**)&p_wqkv, g_wqkv_h);
    cudaGetSymbolAddress((void**)&p_wout, g_wout_h);
    cudaGetSymbolAddress((void**)&p_win, g_win_h);
    cudaGetSymbolAddress((void**)&p_whid, g_whid_h);
    cudaGetSymbolAddress((void**)&p_wgate, g_wgate_h);

    const int SMEM_NT = (2 * 128 * 72 + 2 * 128 * 72) * 2;   // 73728 B
    const int SMEM_NN = (2 * 128 * 72 + 2 * 64 * 136) * 2;   // 71680 B
    const int SMEM_D  = (2 * 64 * 72 + 2 * 128 * 72) * 2;    // 55296 B
    cudaFuncSetAttribute(gemm_d<false, false>,
        cudaFuncAttributeMaxDynamicSharedMemorySize, SMEM_D);
    cudaFuncSetAttribute(gemm_d<true, false>,
        cudaFuncAttributeMaxDynamicSharedMemorySize, SMEM_D);
    cudaFuncSetAttribute(gemm_d<true, true>,
        cudaFuncAttributeMaxDynamicSharedMemorySize, SMEM_D);
    cudaFuncSetAttribute(gemm_h<true, true, false>,
        cudaFuncAttributeMaxDynamicSharedMemorySize, SMEM_NT);
    cudaFuncSetAttribute(gemm_h<false, false, false>,
        cudaFuncAttributeMaxDynamicSharedMemorySize, SMEM_NN);

    const long sQb = (long)LL * QKVN;
    const long sSh = (long)LL * LL;
    const float iscale = 0.08838834764831845f;  // 1/sqrt(128)

    // 0) fused weight pre-conversion to fp16 (ONE launch)
    cvt_all_kernel<<<(int)((CVT_TOTAL + 255) / 256), 256>>>(
        w_qkv, w_out, w_in, w_hid, w_gate,
        p_wqkv, p_wout, p_win, p_whid, p_wgate);

    // 1) attn-branch RMSNorm (half output)
    rmsnorm_kernel<<<TT, 256>>>(x, g_attng, p_xn);

    // 2) QKV GEMM: [4096,2048] x [6144,2048]^T  (half out; high-occ kernel)
    gemm_d<false, false><<<dim3(QKVN / 128, TT / 64), 256, SMEM_D>>>(
        p_xn, p_wqkv, p_qkv, DD, DD, DD, QKVN, 1.0f, nullptr, nullptr, 0);

    // 3+4) L2-resident attention chunking: S(chunk) then softmax(chunk)
    for (int c = 0; c < 8; c++) {
        int b = c >> 2, h0 = (c & 3) * 4;
        const __half* Qb = p_qkv + (long)b * sQb + h0 * HD;
        const __half* Kb = p_qkv + DD + (long)b * sQb + h0 * HD;
        float* Sb = scores + ((long)b * HH + h0) * sSh;
        __half* Pb = p_ph + ((long)b * HH + h0) * sSh;

        gemm_h<true, true, false><<<dim3(LL / 128, LL / 128, 4), 256, SMEM_NT>>>(
            Qb, Kb, Sb, HD, QKVN, QKVN, LL,
            4, 0, HD, 0, HD, 0, sSh, iscale, nullptr, nullptr, 0);

        softmax_kernel<<<4 * LL, 256>>>(Sb, Pb);
    }

    // 5) attn = P V, per (b,h): M=2048, N=128, K=2048 (NN; half out)
    gemm_h<false, false, false><<<dim3(1, LL / 128, BB * HH), 256, SMEM_NN>>>(
        p_ph, p_qkv + 2 * DD, p_attn, LL, LL, QKVN, DD,
        HH, (long)HH * sSh, sSh, sQb, HD, (long)LL * DD, HD,
        1.0f, nullptr, nullptr, 0);

    // 6) after_attn = x + attn * w_out^T  (fp32 out, cached — re-read twice)
    gemm_d<true, false><<<dim3(DD / 128, TT / 64), 256, SMEM_D>>>(
        p_attn, p_wout, p_after, DD, DD, DD, DD, 1.0f, nullptr, x, 0);

    // 7) FFN-branch RMSNorm (half output)
    rmsnorm_kernel<<<TT, 256>>>(p_after, g_ffng, p_yn);

    // 8) hidden = relu(yn * w_in^T)  (half out)
    gemm_d<false, false><<<dim3(DD / 128, TT / 64), 256, SMEM_D>>>(
        p_yn, p_win, p_hidden, DD, DD, DD, DD, 1.0f, nullptr, nullptr, 1);

    // 9) hg = hidden * (hidden * w_gate^T)  (half out)
    gemm_d<false, false><<<dim3(DD / 128, TT / 64), 256, SMEM_D>>>(
        p_hidden, p_wgate, p_hg, DD, DD, DD, DD, 1.0f, p_hidden, nullptr, 0);

    // 10) out = after_attn + hg * w_hidden^T  (fp32 final output, streamed)
    gemm_d<true, true><<<dim3(DD / 128, TT / 64), 256, SMEM_D>>>(
        p_hg, p_whid, out, DD, DD, DD, DD, 1.0f, nullptr, p_after, 0);
}